// round 2
// baseline (speedup 1.0000x reference)
#include <cuda_runtime.h>

#define NN   50000   // nodes
#define KNB  16      // neighbors
#define D    256     // feature dim
#define NC   50      // classes
#define NB   4096    // batch
#define NEG_SLOPE 0.2f

// -------- scratch (static device allocations; no cudaMalloc allowed) --------
__device__ float g_hw[NN * D];   // h @ W for current layer
__device__ float g_h [NN * D];   // layer output (ping buffer)
__device__ float g_src[NN];
__device__ float g_dst[NN];
__device__ float g_ws[D];        // W @ a_src
__device__ float g_wd[D];        // W @ a_dst
__device__ int   g_idx64;        // 1 if index arrays are int64, 0 if int32

__device__ __forceinline__ int load_idx(const void* p, long long i) {
    if (g_idx64) return (int)((const long long*)p)[i];
    return ((const int*)p)[i];
}

__device__ __forceinline__ float warp_red_sum(float v) {
#pragma unroll
    for (int o = 16; o > 0; o >>= 1) v += __shfl_xor_sync(0xffffffffu, v, o);
    return v;
}

// ---------------------------------------------------------------------------
// Probe the index dtype. Reads only words [0, n_words) which exist under
// both interpretations (n_words <= element count). int64 nonneg values
// < 2^31 have every odd 32-bit word == 0; an int32 stream of random node
// ids will violate that almost surely within 1024 samples.
// ---------------------------------------------------------------------------
__global__ void detect_kernel(const int* __restrict__ nb, int n_words) {
    if (threadIdx.x != 0 || blockIdx.x != 0) return;
    int is64 = 1;
    for (int i = 1; i < n_words; i += 2) {
        if (nb[i] != 0) { is64 = 0; break; }
    }
    g_idx64 = is64;
}

// ---------------------------------------------------------------------------
// Fold attention vectors through W:  ws[i] = sum_j W[i][j]*a_s[j]  (and wd).
// ---------------------------------------------------------------------------
__global__ void wvec_kernel(const float* __restrict__ W,
                            const float* __restrict__ a_s,
                            const float* __restrict__ a_d) {
    int i = blockIdx.x;
    int t = threadIdx.x;
    float s1 = 0.f, s2 = 0.f;
    for (int j = t; j < D; j += 128) {
        float w = W[i * D + j];
        s1 += w * a_s[j];
        s2 += w * a_d[j];
    }
    __shared__ float sh1[4], sh2[4];
    s1 = warp_red_sum(s1);
    s2 = warp_red_sum(s2);
    if ((t & 31) == 0) { sh1[t >> 5] = s1; sh2[t >> 5] = s2; }
    __syncthreads();
    if (t == 0) {
        g_ws[i] = sh1[0] + sh1[1] + sh1[2] + sh1[3];
        g_wd[i] = sh2[0] + sh2[1] + sh2[2] + sh2[3];
    }
}

// ---------------------------------------------------------------------------
// src[n] = h[n] . (W a_s),  dst[n] = h[n] . (W a_d).  One warp per node.
// ---------------------------------------------------------------------------
__global__ void srcdst_kernel(const float* __restrict__ Hext, int use_global) {
    const float* H = use_global ? g_h : Hext;
    int w    = (blockIdx.x * blockDim.x + threadIdx.x) >> 5;
    int lane = threadIdx.x & 31;
    if (w >= NN) return;
    const float4* row = (const float4*)(H + (size_t)w * D);
    float4 h0 = row[lane * 2], h1 = row[lane * 2 + 1];
    const float4* ws4 = (const float4*)g_ws;
    const float4* wd4 = (const float4*)g_wd;
    float4 a0 = ws4[lane * 2], a1 = ws4[lane * 2 + 1];
    float4 b0 = wd4[lane * 2], b1 = wd4[lane * 2 + 1];
    float s = h0.x * a0.x + h0.y * a0.y + h0.z * a0.z + h0.w * a0.w
            + h1.x * a1.x + h1.y * a1.y + h1.z * a1.z + h1.w * a1.w;
    float d = h0.x * b0.x + h0.y * b0.y + h0.z * b0.z + h0.w * b0.w
            + h1.x * b1.x + h1.y * b1.y + h1.z * b1.z + h1.w * b1.w;
    s = warp_red_sum(s);
    d = warp_red_sum(d);
    if (lane == 0) { g_src[w] = s; g_dst[w] = d; }
}

// ---------------------------------------------------------------------------
// GEMM: g_hw[M,D] = A[M,D] @ W[D,D].  BM=128, BN=64, BK=16, 256 threads,
// 8x4 register tile per thread.
// ---------------------------------------------------------------------------
#define BM 128
#define BN 64
#define BK 16

__global__ void gemm_kernel(const float* __restrict__ Aext,
                            const float* __restrict__ W,
                            int use_global) {
    const float* A = use_global ? g_h : Aext;
    __shared__ float As[BK][BM];
    __shared__ float Bs[BK][BN];

    int tid = threadIdx.x;
    int tx  = tid & 15;   // N direction (16 * 4 = 64)
    int ty  = tid >> 4;   // M direction (16 * 8 = 128)
    int m0  = blockIdx.y * BM;
    int n0  = blockIdx.x * BN;

    float acc[8][4];
#pragma unroll
    for (int i = 0; i < 8; i++)
#pragma unroll
        for (int j = 0; j < 4; j++) acc[i][j] = 0.f;

    int aRow = tid >> 2;        // 0..63
    int aCol = (tid & 3) * 4;   // 0,4,8,12
    int bRow = tid >> 4;        // 0..15
    int bCol = (tid & 15) * 4;  // 0..60

    for (int k0 = 0; k0 < D; k0 += BK) {
#pragma unroll
        for (int half = 0; half < 2; half++) {
            int row = aRow + half * 64;
            int m   = m0 + row;
            float4 f = make_float4(0.f, 0.f, 0.f, 0.f);
            if (m < NN) f = *(const float4*)(A + (size_t)m * D + k0 + aCol);
            As[aCol + 0][row] = f.x;
            As[aCol + 1][row] = f.y;
            As[aCol + 2][row] = f.z;
            As[aCol + 3][row] = f.w;
        }
        *(float4*)&Bs[bRow][bCol] =
            *(const float4*)(W + (size_t)(k0 + bRow) * D + n0 + bCol);
        __syncthreads();

#pragma unroll
        for (int kk = 0; kk < BK; kk++) {
            float4 b4 = *(const float4*)&Bs[kk][tx * 4];
            float a[8];
#pragma unroll
            for (int i = 0; i < 8; i++) a[i] = As[kk][ty * 8 + i];
#pragma unroll
            for (int i = 0; i < 8; i++) {
                acc[i][0] += a[i] * b4.x;
                acc[i][1] += a[i] * b4.y;
                acc[i][2] += a[i] * b4.z;
                acc[i][3] += a[i] * b4.w;
            }
        }
        __syncthreads();
    }

#pragma unroll
    for (int i = 0; i < 8; i++) {
        int m = m0 + ty * 8 + i;
        if (m < NN) {
            *(float4*)(g_hw + (size_t)m * D + n0 + tx * 4) =
                make_float4(acc[i][0], acc[i][1], acc[i][2], acc[i][3]);
        }
    }
}

// ---------------------------------------------------------------------------
// Attention + aggregation + ELU. One warp per node.
// ---------------------------------------------------------------------------
__global__ void agg_kernel(const void* __restrict__ neighbors) {
    int w    = (blockIdx.x * blockDim.x + threadIdx.x) >> 5;
    int lane = threadIdx.x & 31;
    if (w >= NN) return;

    int   nbr = 0;
    float e   = -1e30f;
    if (lane < KNB) {
        nbr = load_idx(neighbors, (long long)w * KNB + lane);
        e   = g_src[w] + g_dst[nbr];
        e   = e > 0.f ? e : NEG_SLOPE * e;   // LeakyReLU
    }
    float m = e;
#pragma unroll
    for (int o = 8; o > 0; o >>= 1) m = fmaxf(m, __shfl_xor_sync(0xffffffffu, m, o));
    float ex = (lane < KNB) ? __expf(e - m) : 0.f;
    float s = ex;
#pragma unroll
    for (int o = 8; o > 0; o >>= 1) s += __shfl_xor_sync(0xffffffffu, s, o);
    float alpha = ex / s;

    float acc[8] = {0.f, 0.f, 0.f, 0.f, 0.f, 0.f, 0.f, 0.f};
#pragma unroll
    for (int k = 0; k < KNB; k++) {
        float al  = __shfl_sync(0xffffffffu, alpha, k);
        int   idx = __shfl_sync(0xffffffffu, nbr, k);
        const float4* row = (const float4*)(g_hw + (size_t)idx * D);
        float4 v0 = row[lane * 2];
        float4 v1 = row[lane * 2 + 1];
        acc[0] += al * v0.x; acc[1] += al * v0.y;
        acc[2] += al * v0.z; acc[3] += al * v0.w;
        acc[4] += al * v1.x; acc[5] += al * v1.y;
        acc[6] += al * v1.z; acc[7] += al * v1.w;
    }
    float4 o0, o1;  // ELU
    o0.x = acc[0] > 0.f ? acc[0] : __expf(acc[0]) - 1.f;
    o0.y = acc[1] > 0.f ? acc[1] : __expf(acc[1]) - 1.f;
    o0.z = acc[2] > 0.f ? acc[2] : __expf(acc[2]) - 1.f;
    o0.w = acc[3] > 0.f ? acc[3] : __expf(acc[3]) - 1.f;
    o1.x = acc[4] > 0.f ? acc[4] : __expf(acc[4]) - 1.f;
    o1.y = acc[5] > 0.f ? acc[5] : __expf(acc[5]) - 1.f;
    o1.z = acc[6] > 0.f ? acc[6] : __expf(acc[6]) - 1.f;
    o1.w = acc[7] > 0.f ? acc[7] : __expf(acc[7]) - 1.f;
    float4* orow = (float4*)(g_h + (size_t)w * D);
    orow[lane * 2]     = o0;
    orow[lane * 2 + 1] = o1;
}

// ---------------------------------------------------------------------------
// Classification head: out[b] = h[node[b]] @ cls_W^T + cls_b. Warp per b.
// ---------------------------------------------------------------------------
__global__ void cls_kernel(const void* __restrict__ node,
                           const float* __restrict__ cls_W,
                           const float* __restrict__ cls_b,
                           float* __restrict__ out) {
    int b    = (blockIdx.x * blockDim.x + threadIdx.x) >> 5;
    int lane = threadIdx.x & 31;
    if (b >= NB) return;
    int n = load_idx(node, b);
    const float4* hr = (const float4*)(g_h + (size_t)n * D);
    float4 h0 = hr[lane * 2], h1 = hr[lane * 2 + 1];
    for (int c = 0; c < NC; c++) {
        const float4* wr = (const float4*)(cls_W + (size_t)c * D);
        float4 w0 = wr[lane * 2], w1 = wr[lane * 2 + 1];
        float p = h0.x * w0.x + h0.y * w0.y + h0.z * w0.z + h0.w * w0.w
                + h1.x * w1.x + h1.y * w1.y + h1.z * w1.z + h1.w * w1.w;
        p = warp_red_sum(p);
        if (lane == 0) out[(size_t)b * NC + c] = p + cls_b[c];
    }
}

// ---------------------------------------------------------------------------
extern "C" void kernel_launch(void* const* d_in, const int* in_sizes, int n_in,
                              void* d_out, int out_size) {
    const void*  node      = d_in[0];
    const float* node_feat = (const float*)d_in[1];
    const void*  neighbors = d_in[2];
    const float* Ws        = (const float*)d_in[3];
    const float* a_src     = (const float*)d_in[4];
    const float* a_dst     = (const float*)d_in[5];
    const float* cls_W     = (const float*)d_in[6];
    const float* cls_b     = (const float*)d_in[7];
    float* out = (float*)d_out;

    const int warp_blocks = (NN * 32 + 255) / 256;  // 6250

    // Probe whether index arrays are int32 or int64 (safe: reads < count words).
    int n_words = in_sizes[2] < 2048 ? in_sizes[2] : 2048;
    detect_kernel<<<1, 32>>>((const int*)neighbors, n_words);

    for (int l = 0; l < 2; l++) {
        const float* W = Ws + (size_t)l * D * D;
        wvec_kernel<<<D, 128>>>(W, a_src + l * D, a_dst + l * D);
        srcdst_kernel<<<warp_blocks, 256>>>(node_feat, l);
        gemm_kernel<<<dim3(D / BN, (NN + BM - 1) / BM), 256>>>(node_feat, W, l);
        agg_kernel<<<warp_blocks, 256>>>(neighbors);
    }
    cls_kernel<<<(NB * 32 + 255) / 256, 256>>>(node, cls_W, cls_b, out);
}

// round 5
// speedup vs baseline: 1.4758x; 1.4758x over previous
#include <cuda_runtime.h>
#include <cstdint>

#define NN   50000   // nodes
#define KNB  16      // neighbors
#define D    256     // feature dim
#define NC   50      // classes
#define NB   4096    // batch
#define NEG_SLOPE 0.2f

// -------- scratch (static device allocations; no cudaMalloc allowed) --------
__device__ float g_hw[NN * D];   // h @ W for current layer
__device__ float g_h [NN * D];   // layer output (ping buffer)
__device__ float g_src[NN];
__device__ float g_dst[NN];
__device__ int   g_idx64;        // 1 if index arrays are int64, 0 if int32

__device__ __forceinline__ int load_idx(const void* p, long long i) {
    if (g_idx64) return (int)((const long long*)p)[i];
    return ((const int*)p)[i];
}

__device__ __forceinline__ float warp_red_sum(float v) {
#pragma unroll
    for (int o = 16; o > 0; o >>= 1) v += __shfl_xor_sync(0xffffffffu, v, o);
    return v;
}

__device__ __forceinline__ uint32_t f2tf32(float x) {
    uint32_t r;
    asm("cvt.rna.tf32.f32 %0, %1;" : "=r"(r) : "f"(x));
    return r;
}

// ---------------------------------------------------------------------------
// Index dtype probe (reads only words that exist under both interpretations).
// ---------------------------------------------------------------------------
__global__ void detect_kernel(const int* __restrict__ nb, int n_words) {
    if (threadIdx.x != 0 || blockIdx.x != 0) return;
    int is64 = 1;
    for (int i = 1; i < n_words; i += 2) {
        if (nb[i] != 0) { is64 = 0; break; }
    }
    g_idx64 = is64;
}

__global__ void zero_sd_kernel() {
    int i = blockIdx.x * blockDim.x + threadIdx.x;
    if (i < NN) { g_src[i] = 0.f; g_dst[i] = 0.f; }
}

// ---------------------------------------------------------------------------
// tf32 tensor-core GEMM:  g_hw[M,256] = A[M,256] @ W[256,256],
// fused epilogue: g_src[m] += hw[m,:].a_s ; g_dst[m] += hw[m,:].a_d
// BM=128, BN=128, BK=32, 256 threads = 8 warps, warptile 32(M) x 64(N).
// mma.m16n8k8: per warp 2 M-tiles x 8 N-tiles.
// Swizzled smem: As[m][k ^ 4*(m&7)], Bs[k][n ^ 8*(k&3)] -> conflict-free LDS.
// ---------------------------------------------------------------------------
#define GBM 128
#define GBN 128
#define GBK 32

__global__ void __launch_bounds__(256) tc_gemm_kernel(
    const float* __restrict__ Aext, const float* __restrict__ W,
    const float* __restrict__ a_s,  const float* __restrict__ a_d,
    int use_global)
{
    const float* A = use_global ? g_h : Aext;

    __shared__ float As[GBM * GBK];   // [m][k^swz], stride 32
    __shared__ float Bs[GBK * GBN];   // [k][n^swz], stride 128

    const int tid    = threadIdx.x;
    const int wid    = tid >> 5;
    const int lane   = tid & 31;
    const int groupr = lane >> 2;     // 0..7
    const int qk     = lane & 3;      // 0..3
    const int warpM  = wid >> 1;      // 0..3  -> 32 rows each
    const int warpN  = wid & 1;       // 0..1  -> 64 cols each
    const int m0     = blockIdx.y * GBM;
    const int n0     = blockIdx.x * GBN;

    float c[2][8][4];
#pragma unroll
    for (int mt = 0; mt < 2; mt++)
#pragma unroll
        for (int nt = 0; nt < 8; nt++)
#pragma unroll
            for (int j = 0; j < 4; j++) c[mt][nt][j] = 0.f;

    // A-load mapping: thread t -> row t/8 (+32*iter), k4 = (t%8)*4
    const int a_mr = tid >> 3;
    const int a_k4 = (tid & 7) * 4;
    // B-load mapping: thread t -> k row t/32 (+8*iter), n4 = (t%32)*4
    const int b_kr = tid >> 5;
    const int b_n4 = (tid & 31) * 4;

    for (int kb = 0; kb < D; kb += GBK) {
        // ---- stage A tile (with tf32 convert + swizzle) ----
#pragma unroll
        for (int it = 0; it < 4; it++) {
            int mr = a_mr + it * 32;
            int m  = m0 + mr;
            float4 f = make_float4(0.f, 0.f, 0.f, 0.f);
            if (m < NN) f = *(const float4*)(A + (size_t)m * D + kb + a_k4);
            int pk = a_k4 ^ ((mr & 7) * 4);
            float4* dst = (float4*)&As[mr * GBK + pk];
            *dst = make_float4(__uint_as_float(f2tf32(f.x)),
                               __uint_as_float(f2tf32(f.y)),
                               __uint_as_float(f2tf32(f.z)),
                               __uint_as_float(f2tf32(f.w)));
        }
        // ---- stage B tile ----
#pragma unroll
        for (int it = 0; it < 4; it++) {
            int kr = b_kr + it * 8;
            float4 f = *(const float4*)(W + (size_t)(kb + kr) * D + n0 + b_n4);
            int pn = b_n4 ^ ((kr & 3) * 8);
            float4* dst = (float4*)&Bs[kr * GBN + pn];
            *dst = make_float4(__uint_as_float(f2tf32(f.x)),
                               __uint_as_float(f2tf32(f.y)),
                               __uint_as_float(f2tf32(f.z)),
                               __uint_as_float(f2tf32(f.w)));
        }
        __syncthreads();

#pragma unroll
        for (int ks = 0; ks < 4; ks++) {
            const int k0 = ks * 8;
            // A fragments: 2 M-tiles x 4 regs
            uint32_t af[2][4];
#pragma unroll
            for (int mt = 0; mt < 2; mt++) {
                int mlo = warpM * 32 + mt * 16 + groupr;
                int mhi = mlo + 8;
                int swlo = (mlo & 7) * 4;
                int swhi = (mhi & 7) * 4;   // == swlo (adding 8 keeps m&7)
                af[mt][0] = __float_as_uint(As[mlo * GBK + ((k0 + qk)     ^ swlo)]);
                af[mt][1] = __float_as_uint(As[mhi * GBK + ((k0 + qk)     ^ swhi)]);
                af[mt][2] = __float_as_uint(As[mlo * GBK + ((k0 + qk + 4) ^ swlo)]);
                af[mt][3] = __float_as_uint(As[mhi * GBK + ((k0 + qk + 4) ^ swhi)]);
            }
#pragma unroll
            for (int nt = 0; nt < 8; nt++) {
                int n  = warpN * 64 + nt * 8 + groupr;
                int sw = qk * 8;
                uint32_t b0 = __float_as_uint(Bs[(k0 + qk)     * GBN + (n ^ sw)]);
                uint32_t b1 = __float_as_uint(Bs[(k0 + qk + 4) * GBN + (n ^ sw)]);
#pragma unroll
                for (int mt = 0; mt < 2; mt++) {
                    asm volatile(
                        "mma.sync.aligned.m16n8k8.row.col.f32.tf32.tf32.f32 "
                        "{%0,%1,%2,%3}, {%4,%5,%6,%7}, {%8,%9}, {%0,%1,%2,%3};"
                        : "+f"(c[mt][nt][0]), "+f"(c[mt][nt][1]),
                          "+f"(c[mt][nt][2]), "+f"(c[mt][nt][3])
                        : "r"(af[mt][0]), "r"(af[mt][1]),
                          "r"(af[mt][2]), "r"(af[mt][3]),
                          "r"(b0), "r"(b1));
                }
            }
        }
        __syncthreads();
    }

    // ---- epilogue: store hw + fused src/dst partial dots ----
    float sp[2][2] = {{0.f, 0.f}, {0.f, 0.f}};   // [mt][half] src partials
    float dp[2][2] = {{0.f, 0.f}, {0.f, 0.f}};
#pragma unroll
    for (int mt = 0; mt < 2; mt++) {
        int rlo = m0 + warpM * 32 + mt * 16 + groupr;
        int rhi = rlo + 8;
#pragma unroll
        for (int nt = 0; nt < 8; nt++) {
            int col = n0 + warpN * 64 + nt * 8 + 2 * qk;
            float as0 = __ldg(a_s + col), as1 = __ldg(a_s + col + 1);
            float ad0 = __ldg(a_d + col), ad1 = __ldg(a_d + col + 1);
            float v0 = c[mt][nt][0], v1 = c[mt][nt][1];
            float v2 = c[mt][nt][2], v3 = c[mt][nt][3];
            sp[mt][0] += v0 * as0 + v1 * as1;
            dp[mt][0] += v0 * ad0 + v1 * ad1;
            sp[mt][1] += v2 * as0 + v3 * as1;
            dp[mt][1] += v2 * ad0 + v3 * ad1;
            if (rlo < NN) *(float2*)(g_hw + (size_t)rlo * D + col) = make_float2(v0, v1);
            if (rhi < NN) *(float2*)(g_hw + (size_t)rhi * D + col) = make_float2(v2, v3);
        }
    }
    // reduce over the 4 lanes (qk = 0..3) sharing each row, then atomic
#pragma unroll
    for (int mt = 0; mt < 2; mt++)
#pragma unroll
        for (int hf = 0; hf < 2; hf++) {
            float s = sp[mt][hf], d = dp[mt][hf];
            s += __shfl_xor_sync(0xffffffffu, s, 1);
            s += __shfl_xor_sync(0xffffffffu, s, 2);
            d += __shfl_xor_sync(0xffffffffu, d, 1);
            d += __shfl_xor_sync(0xffffffffu, d, 2);
            if (qk == 0) {
                int r = m0 + warpM * 32 + mt * 16 + groupr + hf * 8;
                if (r < NN) {
                    atomicAdd(&g_src[r], s);
                    atomicAdd(&g_dst[r], d);
                }
            }
        }
}

// ---------------------------------------------------------------------------
// Attention + aggregation + ELU. One warp per node.
// ---------------------------------------------------------------------------
__global__ void agg_kernel(const void* __restrict__ neighbors) {
    int w    = (blockIdx.x * blockDim.x + threadIdx.x) >> 5;
    int lane = threadIdx.x & 31;
    if (w >= NN) return;

    int   nbr = 0;
    float e   = -1e30f;
    if (lane < KNB) {
        nbr = load_idx(neighbors, (long long)w * KNB + lane);
        e   = g_src[w] + g_dst[nbr];
        e   = e > 0.f ? e : NEG_SLOPE * e;   // LeakyReLU
    }
    float m = e;
#pragma unroll
    for (int o = 8; o > 0; o >>= 1) m = fmaxf(m, __shfl_xor_sync(0xffffffffu, m, o));
    float ex = (lane < KNB) ? __expf(e - m) : 0.f;
    float s = ex;
#pragma unroll
    for (int o = 8; o > 0; o >>= 1) s += __shfl_xor_sync(0xffffffffu, s, o);
    float alpha = ex / s;

    float acc[8] = {0.f, 0.f, 0.f, 0.f, 0.f, 0.f, 0.f, 0.f};
#pragma unroll
    for (int k = 0; k < KNB; k++) {
        float al  = __shfl_sync(0xffffffffu, alpha, k);
        int   idx = __shfl_sync(0xffffffffu, nbr, k);
        const float4* row = (const float4*)(g_hw + (size_t)idx * D);
        float4 v0 = row[lane * 2];
        float4 v1 = row[lane * 2 + 1];
        acc[0] += al * v0.x; acc[1] += al * v0.y;
        acc[2] += al * v0.z; acc[3] += al * v0.w;
        acc[4] += al * v1.x; acc[5] += al * v1.y;
        acc[6] += al * v1.z; acc[7] += al * v1.w;
    }
    float4 o0, o1;  // ELU
    o0.x = acc[0] > 0.f ? acc[0] : __expf(acc[0]) - 1.f;
    o0.y = acc[1] > 0.f ? acc[1] : __expf(acc[1]) - 1.f;
    o0.z = acc[2] > 0.f ? acc[2] : __expf(acc[2]) - 1.f;
    o0.w = acc[3] > 0.f ? acc[3] : __expf(acc[3]) - 1.f;
    o1.x = acc[4] > 0.f ? acc[4] : __expf(acc[4]) - 1.f;
    o1.y = acc[5] > 0.f ? acc[5] : __expf(acc[5]) - 1.f;
    o1.z = acc[6] > 0.f ? acc[6] : __expf(acc[6]) - 1.f;
    o1.w = acc[7] > 0.f ? acc[7] : __expf(acc[7]) - 1.f;
    float4* orow = (float4*)(g_h + (size_t)w * D);
    orow[lane * 2]     = o0;
    orow[lane * 2 + 1] = o1;
}

// ---------------------------------------------------------------------------
// Classification head: out[b] = h[node[b]] @ cls_W^T + cls_b. Warp per b.
// ---------------------------------------------------------------------------
__global__ void cls_kernel(const void* __restrict__ node,
                           const float* __restrict__ cls_W,
                           const float* __restrict__ cls_b,
                           float* __restrict__ out) {
    int b    = (blockIdx.x * blockDim.x + threadIdx.x) >> 5;
    int lane = threadIdx.x & 31;
    if (b >= NB) return;
    int n = load_idx(node, b);
    const float4* hr = (const float4*)(g_h + (size_t)n * D);
    float4 h0 = hr[lane * 2], h1 = hr[lane * 2 + 1];
    for (int c = 0; c < NC; c++) {
        const float4* wr = (const float4*)(cls_W + (size_t)c * D);
        float4 w0 = wr[lane * 2], w1 = wr[lane * 2 + 1];
        float p = h0.x * w0.x + h0.y * w0.y + h0.z * w0.z + h0.w * w0.w
                + h1.x * w1.x + h1.y * w1.y + h1.z * w1.z + h1.w * w1.w;
        p = warp_red_sum(p);
        if (lane == 0) out[(size_t)b * NC + c] = p + cls_b[c];
    }
}

// ---------------------------------------------------------------------------
extern "C" void kernel_launch(void* const* d_in, const int* in_sizes, int n_in,
                              void* d_out, int out_size) {
    const void*  node      = d_in[0];
    const float* node_feat = (const float*)d_in[1];
    const void*  neighbors = d_in[2];
    const float* Ws        = (const float*)d_in[3];
    const float* a_src     = (const float*)d_in[4];
    const float* a_dst     = (const float*)d_in[5];
    const float* cls_W     = (const float*)d_in[6];
    const float* cls_b     = (const float*)d_in[7];
    float* out = (float*)d_out;

    const int warp_blocks = (NN * 32 + 255) / 256;  // 6250

    int n_words = in_sizes[2] < 2048 ? in_sizes[2] : 2048;
    detect_kernel<<<1, 32>>>((const int*)neighbors, n_words);

    dim3 ggrid(D / GBN, (NN + GBM - 1) / GBM);      // (2, 391)
    for (int l = 0; l < 2; l++) {
        const float* W = Ws + (size_t)l * D * D;
        zero_sd_kernel<<<(NN + 255) / 256, 256>>>();
        tc_gemm_kernel<<<ggrid, 256>>>(node_feat, W, a_src + l * D, a_dst + l * D, l);
        agg_kernel<<<warp_blocks, 256>>>(neighbors);
    }
    cls_kernel<<<(NB * 32 + 255) / 256, 256>>>(node, cls_W, cls_b, out);
}

// round 6
// speedup vs baseline: 1.7321x; 1.1736x over previous
#include <cuda_runtime.h>
#include <cuda_fp16.h>
#include <cstdint>

#define NN   50000   // nodes
#define KNB  16      // neighbors
#define D    256     // feature dim
#define NC   50      // classes
#define NB   4096    // batch
#define NEG_SLOPE 0.2f

// -------- scratch (static device allocations; no cudaMalloc allowed) --------
__device__ __half g_hw_h[NN * D]; // h @ W for current layer (fp16, gather array)
__device__ float  g_h [NN * D];   // layer output (fp32)
__device__ float  g_src[NN];
__device__ float  g_dst[NN];
__device__ int    g_idx64;        // 1 if index arrays are int64, 0 if int32

__device__ __forceinline__ int load_idx(const void* p, long long i) {
    if (g_idx64) return (int)((const long long*)p)[i];
    return ((const int*)p)[i];
}

__device__ __forceinline__ float warp_red_sum(float v) {
#pragma unroll
    for (int o = 16; o > 0; o >>= 1) v += __shfl_xor_sync(0xffffffffu, v, o);
    return v;
}

// ---------------------------------------------------------------------------
// Index dtype probe (reads only words that exist under both interpretations).
// ---------------------------------------------------------------------------
__global__ void detect_kernel(const int* __restrict__ nb, int n_words) {
    if (threadIdx.x != 0 || blockIdx.x != 0) return;
    int is64 = 1;
    for (int i = 1; i < n_words; i += 2) {
        if (nb[i] != 0) { is64 = 0; break; }
    }
    g_idx64 = is64;
}

__global__ void zero_sd_kernel() {
    int i = blockIdx.x * blockDim.x + threadIdx.x;
    if (i < NN) { g_src[i] = 0.f; g_dst[i] = 0.f; }
}

// ---------------------------------------------------------------------------
// fp16 tensor-core GEMM:  g_hw_h[M,256] = fp16( A[M,256] @ W[256,256] ),
// fused epilogue: g_src[m] += hw[m,:].a_s ; g_dst[m] += hw[m,:].a_d  (fp32)
// BM=128, BN=128, BK=32, 256 threads = 8 warps, warptile 32(M) x 64(N).
// mma.m16n8k16.f16 : per warp 2 M-tiles x 8 N-tiles x 2 k-steps per BK.
// A smem [m][k] pad-40; W smem TRANSPOSED [n][k] pad-40 so every fragment
// register is one aligned 4B LDS; stride 80B -> banks 20r+qk mod 32, all
// 32 lanes distinct (conflict-free).
// ---------------------------------------------------------------------------
#define GBM 128
#define GBN 128
#define GBK 32
#define ASTR 40   // halves per A row (32 + 8 pad)
#define BSTR 40   // halves per Wt row

__global__ void __launch_bounds__(256) tc_gemm_kernel(
    const float* __restrict__ Aext, const float* __restrict__ W,
    const float* __restrict__ a_s,  const float* __restrict__ a_d,
    int use_global)
{
    const float* A = use_global ? g_h : Aext;

    __shared__ __half As[GBM * ASTR];   // [m][k]
    __shared__ __half Bs[GBN * BSTR];   // [n][k]  (W transposed)

    const int tid    = threadIdx.x;
    const int wid    = tid >> 5;
    const int lane   = tid & 31;
    const int groupr = lane >> 2;     // 0..7
    const int qk     = lane & 3;      // 0..3
    const int warpM  = wid >> 1;      // 0..3  -> 32 rows each
    const int warpN  = wid & 1;       // 0..1  -> 64 cols each
    const int m0     = blockIdx.y * GBM;
    const int n0     = blockIdx.x * GBN;

    float c[2][8][4];
#pragma unroll
    for (int mt = 0; mt < 2; mt++)
#pragma unroll
        for (int nt = 0; nt < 8; nt++)
#pragma unroll
            for (int j = 0; j < 4; j++) c[mt][nt][j] = 0.f;

    // A-load mapping: thread t -> row t/8 (+32*iter), k4 = (t%8)*4
    const int a_mr = tid >> 3;
    const int a_k4 = (tid & 7) * 4;
    // B-load mapping: thread t -> k row t/32 (+8*iter), n4 = (t%32)*4
    const int b_kr = tid >> 5;
    const int b_n4 = (tid & 31) * 4;

    for (int kb = 0; kb < D; kb += GBK) {
        // ---- stage A tile (fp32 -> fp16) ----
#pragma unroll
        for (int it = 0; it < 4; it++) {
            int mr = a_mr + it * 32;
            int m  = m0 + mr;
            float4 f = make_float4(0.f, 0.f, 0.f, 0.f);
            if (m < NN) f = *(const float4*)(A + (size_t)m * D + kb + a_k4);
            __half2* dst = (__half2*)&As[mr * ASTR + a_k4];
            dst[0] = __floats2half2_rn(f.x, f.y);
            dst[1] = __floats2half2_rn(f.z, f.w);
        }
        // ---- stage W tile transposed: Wt[n][k] ----
#pragma unroll
        for (int it = 0; it < 4; it++) {
            int kr = b_kr + it * 8;   // local k 0..31
            float4 f = *(const float4*)(W + (size_t)(kb + kr) * D + n0 + b_n4);
            Bs[(b_n4 + 0) * BSTR + kr] = __float2half_rn(f.x);
            Bs[(b_n4 + 1) * BSTR + kr] = __float2half_rn(f.y);
            Bs[(b_n4 + 2) * BSTR + kr] = __float2half_rn(f.z);
            Bs[(b_n4 + 3) * BSTR + kr] = __float2half_rn(f.w);
        }
        __syncthreads();

#pragma unroll
        for (int ks = 0; ks < 2; ks++) {
            const int kh = ks * 16 + 2 * qk;   // half offset within row
            uint32_t af[2][4];
#pragma unroll
            for (int mt = 0; mt < 2; mt++) {
                int r = warpM * 32 + mt * 16 + groupr;
                af[mt][0] = *(const uint32_t*)&As[r       * ASTR + kh];
                af[mt][1] = *(const uint32_t*)&As[(r + 8) * ASTR + kh];
                af[mt][2] = *(const uint32_t*)&As[r       * ASTR + kh + 8];
                af[mt][3] = *(const uint32_t*)&As[(r + 8) * ASTR + kh + 8];
            }
#pragma unroll
            for (int nt = 0; nt < 8; nt++) {
                int n = warpN * 64 + nt * 8 + groupr;
                uint32_t b0 = *(const uint32_t*)&Bs[n * BSTR + kh];
                uint32_t b1 = *(const uint32_t*)&Bs[n * BSTR + kh + 8];
#pragma unroll
                for (int mt = 0; mt < 2; mt++) {
                    asm volatile(
                        "mma.sync.aligned.m16n8k16.row.col.f32.f16.f16.f32 "
                        "{%0,%1,%2,%3}, {%4,%5,%6,%7}, {%8,%9}, {%0,%1,%2,%3};"
                        : "+f"(c[mt][nt][0]), "+f"(c[mt][nt][1]),
                          "+f"(c[mt][nt][2]), "+f"(c[mt][nt][3])
                        : "r"(af[mt][0]), "r"(af[mt][1]),
                          "r"(af[mt][2]), "r"(af[mt][3]),
                          "r"(b0), "r"(b1));
                }
            }
        }
        __syncthreads();
    }

    // ---- epilogue: store hw (fp16) + fused src/dst partial dots (fp32) ----
    float sp[2][2] = {{0.f, 0.f}, {0.f, 0.f}};
    float dp[2][2] = {{0.f, 0.f}, {0.f, 0.f}};
#pragma unroll
    for (int mt = 0; mt < 2; mt++) {
        int rlo = m0 + warpM * 32 + mt * 16 + groupr;
        int rhi = rlo + 8;
#pragma unroll
        for (int nt = 0; nt < 8; nt++) {
            int col = n0 + warpN * 64 + nt * 8 + 2 * qk;
            float as0 = __ldg(a_s + col), as1 = __ldg(a_s + col + 1);
            float ad0 = __ldg(a_d + col), ad1 = __ldg(a_d + col + 1);
            float v0 = c[mt][nt][0], v1 = c[mt][nt][1];
            float v2 = c[mt][nt][2], v3 = c[mt][nt][3];
            sp[mt][0] += v0 * as0 + v1 * as1;
            dp[mt][0] += v0 * ad0 + v1 * ad1;
            sp[mt][1] += v2 * as0 + v3 * as1;
            dp[mt][1] += v2 * ad0 + v3 * ad1;
            if (rlo < NN)
                *(__half2*)(g_hw_h + (size_t)rlo * D + col) = __floats2half2_rn(v0, v1);
            if (rhi < NN)
                *(__half2*)(g_hw_h + (size_t)rhi * D + col) = __floats2half2_rn(v2, v3);
        }
    }
#pragma unroll
    for (int mt = 0; mt < 2; mt++)
#pragma unroll
        for (int hf = 0; hf < 2; hf++) {
            float s = sp[mt][hf], d = dp[mt][hf];
            s += __shfl_xor_sync(0xffffffffu, s, 1);
            s += __shfl_xor_sync(0xffffffffu, s, 2);
            d += __shfl_xor_sync(0xffffffffu, d, 1);
            d += __shfl_xor_sync(0xffffffffu, d, 2);
            if (qk == 0) {
                int r = m0 + warpM * 32 + mt * 16 + groupr + hf * 8;
                if (r < NN) {
                    atomicAdd(&g_src[r], s);
                    atomicAdd(&g_dst[r], d);
                }
            }
        }
}

// ---------------------------------------------------------------------------
// Attention + aggregation + ELU. One warp per node. fp16 gather (512B/row):
// each lane loads one uint4 (8 halves) -> whole row in one warp-load.
// ---------------------------------------------------------------------------
__global__ void agg_kernel(const void* __restrict__ neighbors) {
    int w    = (blockIdx.x * blockDim.x + threadIdx.x) >> 5;
    int lane = threadIdx.x & 31;
    if (w >= NN) return;

    int   nbr = 0;
    float e   = -1e30f;
    if (lane < KNB) {
        nbr = load_idx(neighbors, (long long)w * KNB + lane);
        e   = g_src[w] + g_dst[nbr];
        e   = e > 0.f ? e : NEG_SLOPE * e;   // LeakyReLU
    }
    float m = e;
#pragma unroll
    for (int o = 8; o > 0; o >>= 1) m = fmaxf(m, __shfl_xor_sync(0xffffffffu, m, o));
    float ex = (lane < KNB) ? __expf(e - m) : 0.f;
    float s = ex;
#pragma unroll
    for (int o = 8; o > 0; o >>= 1) s += __shfl_xor_sync(0xffffffffu, s, o);
    float alpha = ex / s;

    float acc[8] = {0.f, 0.f, 0.f, 0.f, 0.f, 0.f, 0.f, 0.f};
#pragma unroll
    for (int k = 0; k < KNB; k++) {
        float al  = __shfl_sync(0xffffffffu, alpha, k);
        int   idx = __shfl_sync(0xffffffffu, nbr, k);
        uint4 v = *((const uint4*)(g_hw_h + (size_t)idx * D) + lane);
        const __half2* hp = (const __half2*)&v;
        float2 f0 = __half22float2(hp[0]);
        float2 f1 = __half22float2(hp[1]);
        float2 f2 = __half22float2(hp[2]);
        float2 f3 = __half22float2(hp[3]);
        acc[0] += al * f0.x; acc[1] += al * f0.y;
        acc[2] += al * f1.x; acc[3] += al * f1.y;
        acc[4] += al * f2.x; acc[5] += al * f2.y;
        acc[6] += al * f3.x; acc[7] += al * f3.y;
    }
    float4 o0, o1;  // ELU
    o0.x = acc[0] > 0.f ? acc[0] : __expf(acc[0]) - 1.f;
    o0.y = acc[1] > 0.f ? acc[1] : __expf(acc[1]) - 1.f;
    o0.z = acc[2] > 0.f ? acc[2] : __expf(acc[2]) - 1.f;
    o0.w = acc[3] > 0.f ? acc[3] : __expf(acc[3]) - 1.f;
    o1.x = acc[4] > 0.f ? acc[4] : __expf(acc[4]) - 1.f;
    o1.y = acc[5] > 0.f ? acc[5] : __expf(acc[5]) - 1.f;
    o1.z = acc[6] > 0.f ? acc[6] : __expf(acc[6]) - 1.f;
    o1.w = acc[7] > 0.f ? acc[7] : __expf(acc[7]) - 1.f;
    float4* orow = (float4*)(g_h + (size_t)w * D);
    orow[lane * 2]     = o0;
    orow[lane * 2 + 1] = o1;
}

// ---------------------------------------------------------------------------
// Classification head: out[b] = h[node[b]] @ cls_W^T + cls_b. Warp per b.
// ---------------------------------------------------------------------------
__global__ void cls_kernel(const void* __restrict__ node,
                           const float* __restrict__ cls_W,
                           const float* __restrict__ cls_b,
                           float* __restrict__ out) {
    int b    = (blockIdx.x * blockDim.x + threadIdx.x) >> 5;
    int lane = threadIdx.x & 31;
    if (b >= NB) return;
    int n = load_idx(node, b);
    const float4* hr = (const float4*)(g_h + (size_t)n * D);
    float4 h0 = hr[lane * 2], h1 = hr[lane * 2 + 1];
    for (int c = 0; c < NC; c++) {
        const float4* wr = (const float4*)(cls_W + (size_t)c * D);
        float4 w0 = wr[lane * 2], w1 = wr[lane * 2 + 1];
        float p = h0.x * w0.x + h0.y * w0.y + h0.z * w0.z + h0.w * w0.w
                + h1.x * w1.x + h1.y * w1.y + h1.z * w1.z + h1.w * w1.w;
        p = warp_red_sum(p);
        if (lane == 0) out[(size_t)b * NC + c] = p + cls_b[c];
    }
}

// ---------------------------------------------------------------------------
extern "C" void kernel_launch(void* const* d_in, const int* in_sizes, int n_in,
                              void* d_out, int out_size) {
    const void*  node      = d_in[0];
    const float* node_feat = (const float*)d_in[1];
    const void*  neighbors = d_in[2];
    const float* Ws        = (const float*)d_in[3];
    const float* a_src     = (const float*)d_in[4];
    const float* a_dst     = (const float*)d_in[5];
    const float* cls_W     = (const float*)d_in[6];
    const float* cls_b     = (const float*)d_in[7];
    float* out = (float*)d_out;

    const int warp_blocks = (NN * 32 + 255) / 256;  // 6250

    int n_words = in_sizes[2] < 2048 ? in_sizes[2] : 2048;
    detect_kernel<<<1, 32>>>((const int*)neighbors, n_words);

    dim3 ggrid(D / GBN, (NN + GBM - 1) / GBM);      // (2, 391)
    for (int l = 0; l < 2; l++) {
        const float* W = Ws + (size_t)l * D * D;
        zero_sd_kernel<<<(NN + 255) / 256, 256>>>();
        tc_gemm_kernel<<<ggrid, 256>>>(node_feat, W, a_src + l * D, a_dst + l * D, l);
        agg_kernel<<<warp_blocks, 256>>>(neighbors);
    }
    cls_kernel<<<(NB * 32 + 255) / 256, 256>>>(node, cls_W, cls_b, out);
}

// round 7
// speedup vs baseline: 2.8123x; 1.6237x over previous
#include <cuda_runtime.h>
#include <cuda_fp16.h>
#include <cstdint>

#define NN   50000   // nodes
#define KNB  16      // neighbors
#define D    256     // feature dim
#define NC   50      // classes
#define NB   4096    // batch
#define NEG_SLOPE 0.2f

// -------- scratch (static device allocations; no cudaMalloc allowed) --------
__device__ __half g_hw_h[NN * D]; // h @ W for current layer (fp16, gather array)
__device__ float  g_h [NN * D];   // layer output (fp32)
__device__ float  g_src[2 * NN];  // per-layer logit buffers
__device__ float  g_dst[2 * NN];
__device__ int    g_idx64;        // 1 if index arrays are int64, 0 if int32

__device__ __forceinline__ int load_idx(const void* p, long long i) {
    if (g_idx64) return (int)((const long long*)p)[i];
    return ((const int*)p)[i];
}

__device__ __forceinline__ float warp_red_sum(float v) {
#pragma unroll
    for (int o = 16; o > 0; o >>= 1) v += __shfl_xor_sync(0xffffffffu, v, o);
    return v;
}

// ---------------------------------------------------------------------------
// Index dtype probe, parallel. Reads only words [0, n_words) which exist
// under both interpretations.
// ---------------------------------------------------------------------------
__global__ void detect_kernel(const int* __restrict__ nb, int n_words) {
    int bad = 0;
    for (int i = 1 + 2 * threadIdx.x; i < n_words; i += 2 * blockDim.x)
        if (nb[i] != 0) bad = 1;
    int any = __syncthreads_or(bad);
    if (threadIdx.x == 0) g_idx64 = any ? 0 : 1;
}

__global__ void zero_sd_kernel() {
    int i = blockIdx.x * blockDim.x + threadIdx.x;
    if (i < 2 * NN) { g_src[i] = 0.f; g_dst[i] = 0.f; }
}

// ---------------------------------------------------------------------------
// fp16 tensor-core GEMM:  g_hw_h[M,256] = fp16( A[M,256] @ W[256,256] ),
// fused epilogue: src[m] += hw[m,:].a_s ; dst[m] += hw[m,:].a_d  (fp32)
// BM=128, BN=128, BK=32, 256 threads = 8 warps, warptile 32(M) x 64(N),
// mma.m16n8k16. Fragments via ldmatrix:
//   A smem [m][k], stride 40 halves (80B): row 16B-chunks 5m mod 8 = perm,
//     conflict-free ldmatrix.x4.
//   B smem [k][n] natural layout, stride 136 halves (272B): 17k mod 8 = perm,
//     conflict-free ldmatrix.x2.trans; staging = plain 8B stores, no conflict.
// Register-level pipeline: next tile's LDGs issued before current MMA loop.
// ---------------------------------------------------------------------------
#define GBM 128
#define GBN 128
#define GBK 32
#define ASTR 40    // halves per A row
#define BSTR 136   // halves per B row

__global__ void __launch_bounds__(256) tc_gemm_kernel(
    const float* __restrict__ Aext, const float* __restrict__ W,
    const float* __restrict__ a_s,  const float* __restrict__ a_d,
    int layer)
{
    const float* A = layer ? g_h : Aext;
    float* srcp = g_src + layer * NN;
    float* dstp = g_dst + layer * NN;

    __shared__ __half As[GBM * ASTR];
    __shared__ __half Bs[GBK * BSTR];

    const int tid    = threadIdx.x;
    const int wid    = tid >> 5;
    const int lane   = tid & 31;
    const int groupr = lane >> 2;     // 0..7
    const int qk     = lane & 3;      // 0..3
    const int warpM  = wid >> 1;      // 0..3
    const int warpN  = wid & 1;       // 0..1
    const int m0     = blockIdx.y * GBM;
    const int n0     = blockIdx.x * GBN;

    float c[2][8][4];
#pragma unroll
    for (int mt = 0; mt < 2; mt++)
#pragma unroll
        for (int nt = 0; nt < 8; nt++)
#pragma unroll
            for (int j = 0; j < 4; j++) c[mt][nt][j] = 0.f;

    const int a_mr = tid >> 3;        // 0..31
    const int a_k4 = (tid & 7) * 4;   // 0..28
    const int b_kr = tid >> 5;        // 0..7
    const int b_n4 = (tid & 31) * 4;  // 0..124

    float4 fa[4], fb[4];

    // ---- prologue: load tile kb=0 into registers ----
#pragma unroll
    for (int it = 0; it < 4; it++) {
        int m = m0 + a_mr + it * 32;
        fa[it] = make_float4(0.f, 0.f, 0.f, 0.f);
        if (m < NN) fa[it] = *(const float4*)(A + (size_t)m * D + a_k4);
        fb[it] = *(const float4*)(W + (size_t)(b_kr + it * 8) * D + n0 + b_n4);
    }

    for (int kbi = 0; kbi < D / GBK; kbi++) {
        // ---- store staged registers to smem (fp32 -> fp16) ----
#pragma unroll
        for (int it = 0; it < 4; it++) {
            int mr = a_mr + it * 32;
            __half2 a01 = __floats2half2_rn(fa[it].x, fa[it].y);
            __half2 a23 = __floats2half2_rn(fa[it].z, fa[it].w);
            *(uint2*)&As[mr * ASTR + a_k4] =
                make_uint2(*(uint32_t*)&a01, *(uint32_t*)&a23);
            int kr = b_kr + it * 8;
            __half2 b01 = __floats2half2_rn(fb[it].x, fb[it].y);
            __half2 b23 = __floats2half2_rn(fb[it].z, fb[it].w);
            *(uint2*)&Bs[kr * BSTR + b_n4] =
                make_uint2(*(uint32_t*)&b01, *(uint32_t*)&b23);
        }
        __syncthreads();

        // ---- issue next tile's global loads (overlap with MMA) ----
        if (kbi + 1 < D / GBK) {
            int kb = (kbi + 1) * GBK;
#pragma unroll
            for (int it = 0; it < 4; it++) {
                int m = m0 + a_mr + it * 32;
                fa[it] = make_float4(0.f, 0.f, 0.f, 0.f);
                if (m < NN) fa[it] = *(const float4*)(A + (size_t)m * D + kb + a_k4);
                fb[it] = *(const float4*)(W + (size_t)(kb + b_kr + it * 8) * D + n0 + b_n4);
            }
        }

        // ---- MMA over current smem tile ----
#pragma unroll
        for (int ks = 0; ks < 2; ks++) {
            uint32_t af[2][4];
#pragma unroll
            for (int mt = 0; mt < 2; mt++) {
                int row = warpM * 32 + mt * 16 + (lane & 15);
                int col = ks * 16 + ((lane >> 4) << 3);
                uint32_t addr =
                    (uint32_t)__cvta_generic_to_shared(&As[row * ASTR + col]);
                asm volatile(
                    "ldmatrix.sync.aligned.m8n8.x4.shared.b16 {%0,%1,%2,%3}, [%4];"
                    : "=r"(af[mt][0]), "=r"(af[mt][1]),
                      "=r"(af[mt][2]), "=r"(af[mt][3]) : "r"(addr));
            }
#pragma unroll
            for (int nt = 0; nt < 8; nt++) {
                int krow = ks * 16 + (lane & 15);
                int ncol = warpN * 64 + nt * 8;
                uint32_t baddr =
                    (uint32_t)__cvta_generic_to_shared(&Bs[krow * BSTR + ncol]);
                uint32_t b0, b1;
                asm volatile(
                    "ldmatrix.sync.aligned.m8n8.x2.trans.shared.b16 {%0,%1}, [%2];"
                    : "=r"(b0), "=r"(b1) : "r"(baddr));
#pragma unroll
                for (int mt = 0; mt < 2; mt++) {
                    asm volatile(
                        "mma.sync.aligned.m16n8k16.row.col.f32.f16.f16.f32 "
                        "{%0,%1,%2,%3}, {%4,%5,%6,%7}, {%8,%9}, {%0,%1,%2,%3};"
                        : "+f"(c[mt][nt][0]), "+f"(c[mt][nt][1]),
                          "+f"(c[mt][nt][2]), "+f"(c[mt][nt][3])
                        : "r"(af[mt][0]), "r"(af[mt][1]),
                          "r"(af[mt][2]), "r"(af[mt][3]),
                          "r"(b0), "r"(b1));
                }
            }
        }
        __syncthreads();
    }

    // ---- epilogue: store hw (fp16) + fused src/dst partial dots (fp32) ----
    float sp[2][2] = {{0.f, 0.f}, {0.f, 0.f}};
    float dp[2][2] = {{0.f, 0.f}, {0.f, 0.f}};
#pragma unroll
    for (int mt = 0; mt < 2; mt++) {
        int rlo = m0 + warpM * 32 + mt * 16 + groupr;
        int rhi = rlo + 8;
#pragma unroll
        for (int nt = 0; nt < 8; nt++) {
            int col = n0 + warpN * 64 + nt * 8 + 2 * qk;
            float as0 = __ldg(a_s + col), as1 = __ldg(a_s + col + 1);
            float ad0 = __ldg(a_d + col), ad1 = __ldg(a_d + col + 1);
            float v0 = c[mt][nt][0], v1 = c[mt][nt][1];
            float v2 = c[mt][nt][2], v3 = c[mt][nt][3];
            sp[mt][0] += v0 * as0 + v1 * as1;
            dp[mt][0] += v0 * ad0 + v1 * ad1;
            sp[mt][1] += v2 * as0 + v3 * as1;
            dp[mt][1] += v2 * ad0 + v3 * ad1;
            if (rlo < NN)
                *(__half2*)(g_hw_h + (size_t)rlo * D + col) = __floats2half2_rn(v0, v1);
            if (rhi < NN)
                *(__half2*)(g_hw_h + (size_t)rhi * D + col) = __floats2half2_rn(v2, v3);
        }
    }
#pragma unroll
    for (int mt = 0; mt < 2; mt++)
#pragma unroll
        for (int hf = 0; hf < 2; hf++) {
            float s = sp[mt][hf], d = dp[mt][hf];
            s += __shfl_xor_sync(0xffffffffu, s, 1);
            s += __shfl_xor_sync(0xffffffffu, s, 2);
            d += __shfl_xor_sync(0xffffffffu, d, 1);
            d += __shfl_xor_sync(0xffffffffu, d, 2);
            if (qk == 0) {
                int r = m0 + warpM * 32 + mt * 16 + groupr + hf * 8;
                if (r < NN) {
                    atomicAdd(&srcp[r], s);
                    atomicAdd(&dstp[r], d);
                }
            }
        }
}

// ---------------------------------------------------------------------------
// Attention + aggregation + ELU. One warp per node. fp16 gather (512B/row).
// ---------------------------------------------------------------------------
__global__ void agg_kernel(const void* __restrict__ neighbors, int layer) {
    int w    = (blockIdx.x * blockDim.x + threadIdx.x) >> 5;
    int lane = threadIdx.x & 31;
    if (w >= NN) return;
    const float* srcp = g_src + layer * NN;
    const float* dstp = g_dst + layer * NN;

    int   nbr = 0;
    float e   = -1e30f;
    if (lane < KNB) {
        nbr = load_idx(neighbors, (long long)w * KNB + lane);
        e   = srcp[w] + dstp[nbr];
        e   = e > 0.f ? e : NEG_SLOPE * e;   // LeakyReLU
    }
    float m = e;
#pragma unroll
    for (int o = 8; o > 0; o >>= 1) m = fmaxf(m, __shfl_xor_sync(0xffffffffu, m, o));
    float ex = (lane < KNB) ? __expf(e - m) : 0.f;
    float s = ex;
#pragma unroll
    for (int o = 8; o > 0; o >>= 1) s += __shfl_xor_sync(0xffffffffu, s, o);
    float alpha = ex / s;

    float acc[8] = {0.f, 0.f, 0.f, 0.f, 0.f, 0.f, 0.f, 0.f};
#pragma unroll
    for (int k = 0; k < KNB; k++) {
        float al  = __shfl_sync(0xffffffffu, alpha, k);
        int   idx = __shfl_sync(0xffffffffu, nbr, k);
        uint4 v = *((const uint4*)(g_hw_h + (size_t)idx * D) + lane);
        const __half2* hp = (const __half2*)&v;
        float2 f0 = __half22float2(hp[0]);
        float2 f1 = __half22float2(hp[1]);
        float2 f2 = __half22float2(hp[2]);
        float2 f3 = __half22float2(hp[3]);
        acc[0] += al * f0.x; acc[1] += al * f0.y;
        acc[2] += al * f1.x; acc[3] += al * f1.y;
        acc[4] += al * f2.x; acc[5] += al * f2.y;
        acc[6] += al * f3.x; acc[7] += al * f3.y;
    }
    float4 o0, o1;  // ELU
    o0.x = acc[0] > 0.f ? acc[0] : __expf(acc[0]) - 1.f;
    o0.y = acc[1] > 0.f ? acc[1] : __expf(acc[1]) - 1.f;
    o0.z = acc[2] > 0.f ? acc[2] : __expf(acc[2]) - 1.f;
    o0.w = acc[3] > 0.f ? acc[3] : __expf(acc[3]) - 1.f;
    o1.x = acc[4] > 0.f ? acc[4] : __expf(acc[4]) - 1.f;
    o1.y = acc[5] > 0.f ? acc[5] : __expf(acc[5]) - 1.f;
    o1.z = acc[6] > 0.f ? acc[6] : __expf(acc[6]) - 1.f;
    o1.w = acc[7] > 0.f ? acc[7] : __expf(acc[7]) - 1.f;
    float4* orow = (float4*)(g_h + (size_t)w * D);
    orow[lane * 2]     = o0;
    orow[lane * 2 + 1] = o1;
}

// ---------------------------------------------------------------------------
// Classification head: out[b] = h[node[b]] @ cls_W^T + cls_b. Warp per b.
// ---------------------------------------------------------------------------
__global__ void cls_kernel(const void* __restrict__ node,
                           const float* __restrict__ cls_W,
                           const float* __restrict__ cls_b,
                           float* __restrict__ out) {
    int b    = (blockIdx.x * blockDim.x + threadIdx.x) >> 5;
    int lane = threadIdx.x & 31;
    if (b >= NB) return;
    int n = load_idx(node, b);
    const float4* hr = (const float4*)(g_h + (size_t)n * D);
    float4 h0 = hr[lane * 2], h1 = hr[lane * 2 + 1];
    for (int c = 0; c < NC; c++) {
        const float4* wr = (const float4*)(cls_W + (size_t)c * D);
        float4 w0 = wr[lane * 2], w1 = wr[lane * 2 + 1];
        float p = h0.x * w0.x + h0.y * w0.y + h0.z * w0.z + h0.w * w0.w
                + h1.x * w1.x + h1.y * w1.y + h1.z * w1.z + h1.w * w1.w;
        p = warp_red_sum(p);
        if (lane == 0) out[(size_t)b * NC + c] = p + cls_b[c];
    }
}

// ---------------------------------------------------------------------------
extern "C" void kernel_launch(void* const* d_in, const int* in_sizes, int n_in,
                              void* d_out, int out_size) {
    const void*  node      = d_in[0];
    const float* node_feat = (const float*)d_in[1];
    const void*  neighbors = d_in[2];
    const float* Ws        = (const float*)d_in[3];
    const float* a_src     = (const float*)d_in[4];
    const float* a_dst     = (const float*)d_in[5];
    const float* cls_W     = (const float*)d_in[6];
    const float* cls_b     = (const float*)d_in[7];
    float* out = (float*)d_out;

    const int warp_blocks = (NN * 32 + 255) / 256;  // 6250

    int n_words = in_sizes[2] < 2048 ? in_sizes[2] : 2048;
    detect_kernel<<<1, 256>>>((const int*)neighbors, n_words);
    zero_sd_kernel<<<(2 * NN + 255) / 256, 256>>>();

    dim3 ggrid(D / GBN, (NN + GBM - 1) / GBM);      // (2, 391)
    for (int l = 0; l < 2; l++) {
        const float* W = Ws + (size_t)l * D * D;
        tc_gemm_kernel<<<ggrid, 256>>>(node_feat, W, a_src + l * D, a_dst + l * D, l);
        agg_kernel<<<warp_blocks, 256>>>(neighbors, l);
    }
    cls_kernel<<<(NB * 32 + 255) / 256, 256>>>(node, cls_W, cls_b, out);
}

// round 8
// speedup vs baseline: 2.9721x; 1.0568x over previous
#include <cuda_runtime.h>
#include <cuda_fp16.h>
#include <cstdint>

#define NN   50000   // nodes
#define KNB  16      // neighbors
#define D    256     // feature dim
#define NC   50      // classes
#define NB   4096    // batch
#define NEG_SLOPE 0.2f

// -------- scratch (static device allocations; no cudaMalloc allowed) --------
__device__ __half g_hw_h[NN * D]; // h @ W for current layer (fp16, gather array)
__device__ __half g_h16[NN * D];  // layer output (fp16)
__device__ float  g_src[2 * NN];  // per-layer logit buffers
__device__ float  g_dst[2 * NN];
__device__ int    g_idx64;        // 1 if index arrays are int64, 0 if int32

__device__ __forceinline__ int load_idx(const void* p, long long i) {
    if (g_idx64) return (int)((const long long*)p)[i];
    return ((const int*)p)[i];
}

__device__ __forceinline__ float warp_red_sum(float v) {
#pragma unroll
    for (int o = 16; o > 0; o >>= 1) v += __shfl_xor_sync(0xffffffffu, v, o);
    return v;
}

// ---------------------------------------------------------------------------
// Index dtype probe, parallel.
// ---------------------------------------------------------------------------
__global__ void detect_kernel(const int* __restrict__ nb, int n_words) {
    int bad = 0;
    for (int i = 1 + 2 * threadIdx.x; i < n_words; i += 2 * blockDim.x)
        if (nb[i] != 0) bad = 1;
    int any = __syncthreads_or(bad);
    if (threadIdx.x == 0) g_idx64 = any ? 0 : 1;
}

__global__ void zero_sd_kernel() {
    int i = blockIdx.x * blockDim.x + threadIdx.x;
    if (i < 2 * NN) { g_src[i] = 0.f; g_dst[i] = 0.f; }
}

// ---------------------------------------------------------------------------
// fp16 tensor-core GEMM with double-buffered smem (1 barrier / K-tile).
//   g_hw_h[M,256] = fp16( A[M,256] @ W[256,256] )
//   fused: src[m] += hw.a_s ; dst[m] += hw.a_d  (fp32)
// BM=128, BN=128, BK=32, 8 warps, warptile 32x64, mma.m16n8k16.
// A smem [m][k] stride-40 (5m mod 8 perm -> conflict-free ldmatrix.x4).
// B smem [k][n] stride-136 (17k mod 8 perm -> conflict-free ldmatrix.x4.trans,
//   each covering 2 N-tiles).
// Layer 0 reads fp32 node_feat (cvt at staging); layer 1 reads fp16 g_h16.
// ---------------------------------------------------------------------------
#define GBM 128
#define GBN 128
#define GBK 32
#define ASTR 40    // halves per A row
#define BSTR 136   // halves per B row
#define NKB  (D / GBK)   // 8

__global__ void __launch_bounds__(256) tc_gemm_kernel(
    const float* __restrict__ Aext, const float* __restrict__ W,
    const float* __restrict__ a_s,  const float* __restrict__ a_d,
    int layer)
{
    float* srcp = g_src + layer * NN;
    float* dstp = g_dst + layer * NN;

    __shared__ __half As[2][GBM * ASTR];
    __shared__ __half Bs[2][GBK * BSTR];

    const int tid    = threadIdx.x;
    const int wid    = tid >> 5;
    const int lane   = tid & 31;
    const int groupr = lane >> 2;     // 0..7
    const int qk     = lane & 3;      // 0..3
    const int warpM  = wid >> 1;      // 0..3
    const int warpN  = wid & 1;       // 0..1
    const int m0     = blockIdx.y * GBM;
    const int n0     = blockIdx.x * GBN;

    float c[2][8][4];
#pragma unroll
    for (int mt = 0; mt < 2; mt++)
#pragma unroll
        for (int nt = 0; nt < 8; nt++)
#pragma unroll
            for (int j = 0; j < 4; j++) c[mt][nt][j] = 0.f;

    const int a_mr = tid >> 3;        // 0..31
    const int a_k4 = (tid & 7) * 4;   // 0..28
    const int b_kr = tid >> 5;        // 0..7
    const int b_n4 = (tid & 31) * 4;  // 0..124

    float4 fa[4];      // layer-0 staging (fp32)
    uint2  ua[4];      // layer-1 staging (fp16)
    float4 fb[4];      // W staging

    // ---- load K-tile 0 ----
#pragma unroll
    for (int it = 0; it < 4; it++) {
        int m = m0 + a_mr + it * 32;
        if (layer) {
            ua[it] = make_uint2(0u, 0u);
            if (m < NN) ua[it] = *(const uint2*)(g_h16 + (size_t)m * D + a_k4);
        } else {
            fa[it] = make_float4(0.f, 0.f, 0.f, 0.f);
            if (m < NN) fa[it] = *(const float4*)(Aext + (size_t)m * D + a_k4);
        }
        fb[it] = *(const float4*)(W + (size_t)(b_kr + it * 8) * D + n0 + b_n4);
    }
    // ---- store K-tile 0 into buffer 0 ----
#pragma unroll
    for (int it = 0; it < 4; it++) {
        int mr = a_mr + it * 32;
        if (layer) {
            *(uint2*)&As[0][mr * ASTR + a_k4] = ua[it];
        } else {
            __half2 a01 = __floats2half2_rn(fa[it].x, fa[it].y);
            __half2 a23 = __floats2half2_rn(fa[it].z, fa[it].w);
            *(uint2*)&As[0][mr * ASTR + a_k4] =
                make_uint2(*(uint32_t*)&a01, *(uint32_t*)&a23);
        }
        int kr = b_kr + it * 8;
        __half2 b01 = __floats2half2_rn(fb[it].x, fb[it].y);
        __half2 b23 = __floats2half2_rn(fb[it].z, fb[it].w);
        *(uint2*)&Bs[0][kr * BSTR + b_n4] =
            make_uint2(*(uint32_t*)&b01, *(uint32_t*)&b23);
    }
    __syncthreads();

    for (int kbi = 0; kbi < NKB; kbi++) {
        const int cur = kbi & 1;

        // ---- issue next tile's global loads ----
        if (kbi + 1 < NKB) {
            int kb = (kbi + 1) * GBK;
#pragma unroll
            for (int it = 0; it < 4; it++) {
                int m = m0 + a_mr + it * 32;
                if (layer) {
                    ua[it] = make_uint2(0u, 0u);
                    if (m < NN) ua[it] = *(const uint2*)(g_h16 + (size_t)m * D + kb + a_k4);
                } else {
                    fa[it] = make_float4(0.f, 0.f, 0.f, 0.f);
                    if (m < NN) fa[it] = *(const float4*)(Aext + (size_t)m * D + kb + a_k4);
                }
                fb[it] = *(const float4*)(W + (size_t)(kb + b_kr + it * 8) * D + n0 + b_n4);
            }
        }

        // ---- MMA over current buffer ----
#pragma unroll
        for (int ks = 0; ks < 2; ks++) {
            uint32_t af[2][4];
#pragma unroll
            for (int mt = 0; mt < 2; mt++) {
                int row = warpM * 32 + mt * 16 + (lane & 15);
                int col = ks * 16 + ((lane >> 4) << 3);
                uint32_t addr =
                    (uint32_t)__cvta_generic_to_shared(&As[cur][row * ASTR + col]);
                asm volatile(
                    "ldmatrix.sync.aligned.m8n8.x4.shared.b16 {%0,%1,%2,%3}, [%4];"
                    : "=r"(af[mt][0]), "=r"(af[mt][1]),
                      "=r"(af[mt][2]), "=r"(af[mt][3]) : "r"(addr));
            }
#pragma unroll
            for (int np = 0; np < 4; np++) {     // N-tile pairs
                int krow = ks * 16 + ((lane & 8) ? 8 : 0) + (lane & 7);
                int ncol = warpN * 64 + np * 16 + ((lane & 16) ? 8 : 0);
                uint32_t baddr =
                    (uint32_t)__cvta_generic_to_shared(&Bs[cur][krow * BSTR + ncol]);
                uint32_t b0, b1, b2, b3;
                asm volatile(
                    "ldmatrix.sync.aligned.m8n8.x4.trans.shared.b16 {%0,%1,%2,%3}, [%4];"
                    : "=r"(b0), "=r"(b1), "=r"(b2), "=r"(b3) : "r"(baddr));
#pragma unroll
                for (int mt = 0; mt < 2; mt++) {
                    asm volatile(
                        "mma.sync.aligned.m16n8k16.row.col.f32.f16.f16.f32 "
                        "{%0,%1,%2,%3}, {%4,%5,%6,%7}, {%8,%9}, {%0,%1,%2,%3};"
                        : "+f"(c[mt][2*np][0]), "+f"(c[mt][2*np][1]),
                          "+f"(c[mt][2*np][2]), "+f"(c[mt][2*np][3])
                        : "r"(af[mt][0]), "r"(af[mt][1]),
                          "r"(af[mt][2]), "r"(af[mt][3]),
                          "r"(b0), "r"(b1));
                    asm volatile(
                        "mma.sync.aligned.m16n8k16.row.col.f32.f16.f16.f32 "
                        "{%0,%1,%2,%3}, {%4,%5,%6,%7}, {%8,%9}, {%0,%1,%2,%3};"
                        : "+f"(c[mt][2*np+1][0]), "+f"(c[mt][2*np+1][1]),
                          "+f"(c[mt][2*np+1][2]), "+f"(c[mt][2*np+1][3])
                        : "r"(af[mt][0]), "r"(af[mt][1]),
                          "r"(af[mt][2]), "r"(af[mt][3]),
                          "r"(b2), "r"(b3));
                }
            }
        }

        // ---- store staged regs into the other buffer ----
        if (kbi + 1 < NKB) {
            const int nxt = cur ^ 1;
#pragma unroll
            for (int it = 0; it < 4; it++) {
                int mr = a_mr + it * 32;
                if (layer) {
                    *(uint2*)&As[nxt][mr * ASTR + a_k4] = ua[it];
                } else {
                    __half2 a01 = __floats2half2_rn(fa[it].x, fa[it].y);
                    __half2 a23 = __floats2half2_rn(fa[it].z, fa[it].w);
                    *(uint2*)&As[nxt][mr * ASTR + a_k4] =
                        make_uint2(*(uint32_t*)&a01, *(uint32_t*)&a23);
                }
                int kr = b_kr + it * 8;
                __half2 b01 = __floats2half2_rn(fb[it].x, fb[it].y);
                __half2 b23 = __floats2half2_rn(fb[it].z, fb[it].w);
                *(uint2*)&Bs[nxt][kr * BSTR + b_n4] =
                    make_uint2(*(uint32_t*)&b01, *(uint32_t*)&b23);
            }
        }
        __syncthreads();
    }

    // ---- epilogue: store hw (fp16) + fused src/dst partial dots (fp32) ----
    float sp[2][2] = {{0.f, 0.f}, {0.f, 0.f}};
    float dp[2][2] = {{0.f, 0.f}, {0.f, 0.f}};
#pragma unroll
    for (int mt = 0; mt < 2; mt++) {
        int rlo = m0 + warpM * 32 + mt * 16 + groupr;
        int rhi = rlo + 8;
#pragma unroll
        for (int nt = 0; nt < 8; nt++) {
            int col = n0 + warpN * 64 + nt * 8 + 2 * qk;
            float as0 = __ldg(a_s + col), as1 = __ldg(a_s + col + 1);
            float ad0 = __ldg(a_d + col), ad1 = __ldg(a_d + col + 1);
            float v0 = c[mt][nt][0], v1 = c[mt][nt][1];
            float v2 = c[mt][nt][2], v3 = c[mt][nt][3];
            sp[mt][0] += v0 * as0 + v1 * as1;
            dp[mt][0] += v0 * ad0 + v1 * ad1;
            sp[mt][1] += v2 * as0 + v3 * as1;
            dp[mt][1] += v2 * ad0 + v3 * ad1;
            if (rlo < NN)
                *(__half2*)(g_hw_h + (size_t)rlo * D + col) = __floats2half2_rn(v0, v1);
            if (rhi < NN)
                *(__half2*)(g_hw_h + (size_t)rhi * D + col) = __floats2half2_rn(v2, v3);
        }
    }
#pragma unroll
    for (int mt = 0; mt < 2; mt++)
#pragma unroll
        for (int hf = 0; hf < 2; hf++) {
            float s = sp[mt][hf], d = dp[mt][hf];
            s += __shfl_xor_sync(0xffffffffu, s, 1);
            s += __shfl_xor_sync(0xffffffffu, s, 2);
            d += __shfl_xor_sync(0xffffffffu, d, 1);
            d += __shfl_xor_sync(0xffffffffu, d, 2);
            if (qk == 0) {
                int r = m0 + warpM * 32 + mt * 16 + groupr + hf * 8;
                if (r < NN) {
                    atomicAdd(&srcp[r], s);
                    atomicAdd(&dstp[r], d);
                }
            }
        }
}

// ---------------------------------------------------------------------------
// Attention + aggregation + ELU. One warp per node; fp16 gather + fp16 output.
// ---------------------------------------------------------------------------
__global__ void agg_kernel(const void* __restrict__ neighbors, int layer) {
    int w    = (blockIdx.x * blockDim.x + threadIdx.x) >> 5;
    int lane = threadIdx.x & 31;
    if (w >= NN) return;
    const float* srcp = g_src + layer * NN;
    const float* dstp = g_dst + layer * NN;

    int   nbr = 0;
    float e   = -1e30f;
    if (lane < KNB) {
        nbr = load_idx(neighbors, (long long)w * KNB + lane);
        e   = srcp[w] + dstp[nbr];
        e   = e > 0.f ? e : NEG_SLOPE * e;   // LeakyReLU
    }
    float m = e;
#pragma unroll
    for (int o = 8; o > 0; o >>= 1) m = fmaxf(m, __shfl_xor_sync(0xffffffffu, m, o));
    float ex = (lane < KNB) ? __expf(e - m) : 0.f;
    float s = ex;
#pragma unroll
    for (int o = 8; o > 0; o >>= 1) s += __shfl_xor_sync(0xffffffffu, s, o);
    float alpha = ex / s;

    float acc[8] = {0.f, 0.f, 0.f, 0.f, 0.f, 0.f, 0.f, 0.f};
#pragma unroll
    for (int k = 0; k < KNB; k++) {
        float al  = __shfl_sync(0xffffffffu, alpha, k);
        int   idx = __shfl_sync(0xffffffffu, nbr, k);
        uint4 v = *((const uint4*)(g_hw_h + (size_t)idx * D) + lane);
        const __half2* hp = (const __half2*)&v;
        float2 f0 = __half22float2(hp[0]);
        float2 f1 = __half22float2(hp[1]);
        float2 f2 = __half22float2(hp[2]);
        float2 f3 = __half22float2(hp[3]);
        acc[0] += al * f0.x; acc[1] += al * f0.y;
        acc[2] += al * f1.x; acc[3] += al * f1.y;
        acc[4] += al * f2.x; acc[5] += al * f2.y;
        acc[6] += al * f3.x; acc[7] += al * f3.y;
    }
#pragma unroll
    for (int j = 0; j < 8; j++)
        acc[j] = acc[j] > 0.f ? acc[j] : __expf(acc[j]) - 1.f;   // ELU

    uint4 ov;
    __half2* op = (__half2*)&ov;
    op[0] = __floats2half2_rn(acc[0], acc[1]);
    op[1] = __floats2half2_rn(acc[2], acc[3]);
    op[2] = __floats2half2_rn(acc[4], acc[5]);
    op[3] = __floats2half2_rn(acc[6], acc[7]);
    *((uint4*)(g_h16 + (size_t)w * D) + lane) = ov;
}

// ---------------------------------------------------------------------------
// Classification head: out[b] = h[node[b]] @ cls_W^T + cls_b. Warp per b.
// ---------------------------------------------------------------------------
__global__ void cls_kernel(const void* __restrict__ node,
                           const float* __restrict__ cls_W,
                           const float* __restrict__ cls_b,
                           float* __restrict__ out) {
    int b    = (blockIdx.x * blockDim.x + threadIdx.x) >> 5;
    int lane = threadIdx.x & 31;
    if (b >= NB) return;
    int n = load_idx(node, b);
    uint4 v = *((const uint4*)(g_h16 + (size_t)n * D) + lane);
    const __half2* hp = (const __half2*)&v;
    float2 f0 = __half22float2(hp[0]);
    float2 f1 = __half22float2(hp[1]);
    float2 f2 = __half22float2(hp[2]);
    float2 f3 = __half22float2(hp[3]);
    for (int c = 0; c < NC; c++) {
        const float4* wr = (const float4*)(cls_W + (size_t)c * D);
        float4 w0 = wr[lane * 2], w1 = wr[lane * 2 + 1];
        float p = f0.x * w0.x + f0.y * w0.y + f1.x * w0.z + f1.y * w0.w
                + f2.x * w1.x + f2.y * w1.y + f3.x * w1.z + f3.y * w1.w;
        p = warp_red_sum(p);
        if (lane == 0) out[(size_t)b * NC + c] = p + cls_b[c];
    }
}

// ---------------------------------------------------------------------------
extern "C" void kernel_launch(void* const* d_in, const int* in_sizes, int n_in,
                              void* d_out, int out_size) {
    const void*  node      = d_in[0];
    const float* node_feat = (const float*)d_in[1];
    const void*  neighbors = d_in[2];
    const float* Ws        = (const float*)d_in[3];
    const float* a_src     = (const float*)d_in[4];
    const float* a_dst     = (const float*)d_in[5];
    const float* cls_W     = (const float*)d_in[6];
    const float* cls_b     = (const float*)d_in[7];
    float* out = (float*)d_out;

    const int warp_blocks = (NN * 32 + 255) / 256;  // 6250

    int n_words = in_sizes[2] < 2048 ? in_sizes[2] : 2048;
    detect_kernel<<<1, 256>>>((const int*)neighbors, n_words);
    zero_sd_kernel<<<(2 * NN + 255) / 256, 256>>>();

    dim3 ggrid(D / GBN, (NN + GBM - 1) / GBM);      // (2, 391)
    for (int l = 0; l < 2; l++) {
        const float* W = Ws + (size_t)l * D * D;
        tc_gemm_kernel<<<ggrid, 256>>>(node_feat, W, a_src + l * D, a_dst + l * D, l);
        agg_kernel<<<warp_blocks, 256>>>(neighbors, l);
    }
    cls_kernel<<<(NB * 32 + 255) / 256, 256>>>(node, cls_W, cls_b, out);
}

// round 9
// speedup vs baseline: 3.0412x; 1.0233x over previous
#include <cuda_runtime.h>
#include <cuda_fp16.h>
#include <cstdint>

#define NN   50000   // nodes
#define KNB  16      // neighbors
#define D    256     // feature dim
#define NC   50      // classes
#define NB   4096    // batch
#define NEG_SLOPE 0.2f

// -------- scratch (static device allocations; no cudaMalloc allowed) --------
__device__ __half g_hw_h[NN * D];   // h @ W (fp16, gather array)
__device__ __half g_h16[NN * D];    // layer output (fp16)
__device__ __half g_w16[2 * D * D]; // fp16 copies of both layer weights
__device__ float  g_src[2 * NN];
__device__ float  g_dst[2 * NN];
__device__ int    g_idx64;

__device__ __forceinline__ int load_idx(const void* p, long long i) {
    if (g_idx64) return (int)((const long long*)p)[i];
    return ((const int*)p)[i];
}

__device__ __forceinline__ float warp_red_sum(float v) {
#pragma unroll
    for (int o = 16; o > 0; o >>= 1) v += __shfl_xor_sync(0xffffffffu, v, o);
    return v;
}

#define CP_ASYNC16(dst_u32, src) \
    asm volatile("cp.async.cg.shared.global [%0], [%1], 16;" :: "r"(dst_u32), "l"(src))
#define CP_COMMIT() asm volatile("cp.async.commit_group;")
#define CP_WAIT1()  asm volatile("cp.async.wait_group 1;")
#define CP_WAIT0()  asm volatile("cp.async.wait_group 0;")

// ---------------------------------------------------------------------------
// init: zero src/dst, convert W -> fp16, detect index dtype (block 0).
// ---------------------------------------------------------------------------
__global__ void init_kernel(const float* __restrict__ Ws,
                            const int* __restrict__ nb, int n_words) {
    int i = blockIdx.x * blockDim.x + threadIdx.x;
    if (i < 2 * NN) { g_src[i] = 0.f; g_dst[i] = 0.f; }
    if (i < 2 * D * D / 4) {
        float4 f = ((const float4*)Ws)[i];
        __half2 h01 = __floats2half2_rn(f.x, f.y);
        __half2 h23 = __floats2half2_rn(f.z, f.w);
        ((uint2*)g_w16)[i] = make_uint2(*(uint32_t*)&h01, *(uint32_t*)&h23);
    }
    if (blockIdx.x == 0) {
        int bad = 0;
        for (int j = 1 + 2 * threadIdx.x; j < n_words; j += 2 * blockDim.x)
            if (nb[j] != 0) bad = 1;
        int any = __syncthreads_or(bad);
        if (threadIdx.x == 0) g_idx64 = any ? 0 : 1;
    }
}

// ---------------------------------------------------------------------------
// fp16 tensor-core GEMM, 1 barrier per K-tile:
//   A: register-staged 1 tile ahead into As[2] (L0: fp32 LDG+cvt; L1: fp16 LDG)
//   B: cp.async 16B, 3-stage Bs[3] from pre-converted g_w16, 2 tiles ahead
// Fused epilogue: src/dst dot products + fp16 hw store.
// ---------------------------------------------------------------------------
#define GBM 128
#define GBN 128
#define GBK 32
#define ASTR 40
#define BSTR 136
#define NKB  (D / GBK)   // 8

template <int LAYER>
__global__ void __launch_bounds__(256) tc_gemm_kernel(
    const float* __restrict__ Aext,
    const float* __restrict__ a_s, const float* __restrict__ a_d)
{
    float* srcp = g_src + LAYER * NN;
    float* dstp = g_dst + LAYER * NN;
    const __half* Wl = g_w16 + LAYER * D * D;

    __shared__ __half As[2][GBM * ASTR];
    __shared__ __half Bs[3][GBK * BSTR];

    const int tid    = threadIdx.x;
    const int wid    = tid >> 5;
    const int lane   = tid & 31;
    const int groupr = lane >> 2;
    const int qk     = lane & 3;
    const int warpM  = wid >> 1;
    const int warpN  = wid & 1;
    const int m0     = blockIdx.y * GBM;
    const int n0     = blockIdx.x * GBN;

    float c[2][8][4];
#pragma unroll
    for (int mt = 0; mt < 2; mt++)
#pragma unroll
        for (int nt = 0; nt < 8; nt++)
#pragma unroll
            for (int j = 0; j < 4; j++) c[mt][nt][j] = 0.f;

    const int a_mr = tid >> 3;        // 0..31
    const int a_k4 = (tid & 7) * 4;   // 0..28

    float4 fa[4];   // L0 staging
    uint2  ua[4];   // L1 staging

    // B chunk mapping: c = tid, tid+256 -> krow = c>>4 (0..31), nch = c&15
    auto issue_B = [&](int kt) {
#pragma unroll
        for (int rep = 0; rep < 2; rep++) {
            int cch  = tid + rep * 256;
            int krow = cch >> 4;
            int nch  = cch & 15;
            const __half* src = Wl + (size_t)(kt * GBK + krow) * D + n0 + nch * 8;
            uint32_t dst = (uint32_t)__cvta_generic_to_shared(
                &Bs[kt % 3][krow * BSTR + nch * 8]);
            CP_ASYNC16(dst, src);
        }
        CP_COMMIT();
    };
    auto load_A = [&](int kt) {
        int kb = kt * GBK;
#pragma unroll
        for (int it = 0; it < 4; it++) {
            int m = m0 + a_mr + it * 32;
            if (LAYER) {
                ua[it] = make_uint2(0u, 0u);
                if (m < NN) ua[it] = *(const uint2*)(g_h16 + (size_t)m * D + kb + a_k4);
            } else {
                fa[it] = make_float4(0.f, 0.f, 0.f, 0.f);
                if (m < NN) fa[it] = *(const float4*)(Aext + (size_t)m * D + kb + a_k4);
            }
        }
    };
    auto sts_A = [&](int kt) {
        __half* buf = As[kt & 1];
#pragma unroll
        for (int it = 0; it < 4; it++) {
            int mr = a_mr + it * 32;
            if (LAYER) {
                *(uint2*)&buf[mr * ASTR + a_k4] = ua[it];
            } else {
                __half2 a01 = __floats2half2_rn(fa[it].x, fa[it].y);
                __half2 a23 = __floats2half2_rn(fa[it].z, fa[it].w);
                *(uint2*)&buf[mr * ASTR + a_k4] =
                    make_uint2(*(uint32_t*)&a01, *(uint32_t*)&a23);
            }
        }
    };

    // ---- prologue ----
    load_A(0); sts_A(0); load_A(1);
    issue_B(0);
    issue_B(1);

    for (int kbi = 0; kbi < NKB; kbi++) {
        if (kbi == NKB - 1) CP_WAIT0(); else CP_WAIT1();
        __syncthreads();
        if (kbi + 2 < NKB) issue_B(kbi + 2);
        if (kbi + 1 < NKB) sts_A(kbi + 1);
        if (kbi + 2 < NKB) load_A(kbi + 2);

        const __half* Ab = As[kbi & 1];
        const __half* Bb = Bs[kbi % 3];
#pragma unroll
        for (int ks = 0; ks < 2; ks++) {
            uint32_t af[2][4];
#pragma unroll
            for (int mt = 0; mt < 2; mt++) {
                int row = warpM * 32 + mt * 16 + (lane & 15);
                int col = ks * 16 + ((lane >> 4) << 3);
                uint32_t addr =
                    (uint32_t)__cvta_generic_to_shared(&Ab[row * ASTR + col]);
                asm volatile(
                    "ldmatrix.sync.aligned.m8n8.x4.shared.b16 {%0,%1,%2,%3}, [%4];"
                    : "=r"(af[mt][0]), "=r"(af[mt][1]),
                      "=r"(af[mt][2]), "=r"(af[mt][3]) : "r"(addr));
            }
#pragma unroll
            for (int np = 0; np < 4; np++) {
                int krow = ks * 16 + ((lane & 8) ? 8 : 0) + (lane & 7);
                int ncol = warpN * 64 + np * 16 + ((lane & 16) ? 8 : 0);
                uint32_t baddr =
                    (uint32_t)__cvta_generic_to_shared(&Bb[krow * BSTR + ncol]);
                uint32_t b0, b1, b2, b3;
                asm volatile(
                    "ldmatrix.sync.aligned.m8n8.x4.trans.shared.b16 {%0,%1,%2,%3}, [%4];"
                    : "=r"(b0), "=r"(b1), "=r"(b2), "=r"(b3) : "r"(baddr));
#pragma unroll
                for (int mt = 0; mt < 2; mt++) {
                    asm volatile(
                        "mma.sync.aligned.m16n8k16.row.col.f32.f16.f16.f32 "
                        "{%0,%1,%2,%3}, {%4,%5,%6,%7}, {%8,%9}, {%0,%1,%2,%3};"
                        : "+f"(c[mt][2*np][0]), "+f"(c[mt][2*np][1]),
                          "+f"(c[mt][2*np][2]), "+f"(c[mt][2*np][3])
                        : "r"(af[mt][0]), "r"(af[mt][1]),
                          "r"(af[mt][2]), "r"(af[mt][3]),
                          "r"(b0), "r"(b1));
                    asm volatile(
                        "mma.sync.aligned.m16n8k16.row.col.f32.f16.f16.f32 "
                        "{%0,%1,%2,%3}, {%4,%5,%6,%7}, {%8,%9}, {%0,%1,%2,%3};"
                        : "+f"(c[mt][2*np+1][0]), "+f"(c[mt][2*np+1][1]),
                          "+f"(c[mt][2*np+1][2]), "+f"(c[mt][2*np+1][3])
                        : "r"(af[mt][0]), "r"(af[mt][1]),
                          "r"(af[mt][2]), "r"(af[mt][3]),
                          "r"(b2), "r"(b3));
                }
            }
        }
    }

    // ---- epilogue ----
    float sp[2][2] = {{0.f, 0.f}, {0.f, 0.f}};
    float dp[2][2] = {{0.f, 0.f}, {0.f, 0.f}};
#pragma unroll
    for (int mt = 0; mt < 2; mt++) {
        int rlo = m0 + warpM * 32 + mt * 16 + groupr;
        int rhi = rlo + 8;
#pragma unroll
        for (int nt = 0; nt < 8; nt++) {
            int col = n0 + warpN * 64 + nt * 8 + 2 * qk;
            float as0 = __ldg(a_s + col), as1 = __ldg(a_s + col + 1);
            float ad0 = __ldg(a_d + col), ad1 = __ldg(a_d + col + 1);
            float v0 = c[mt][nt][0], v1 = c[mt][nt][1];
            float v2 = c[mt][nt][2], v3 = c[mt][nt][3];
            sp[mt][0] += v0 * as0 + v1 * as1;
            dp[mt][0] += v0 * ad0 + v1 * ad1;
            sp[mt][1] += v2 * as0 + v3 * as1;
            dp[mt][1] += v2 * ad0 + v3 * ad1;
            if (rlo < NN)
                *(__half2*)(g_hw_h + (size_t)rlo * D + col) = __floats2half2_rn(v0, v1);
            if (rhi < NN)
                *(__half2*)(g_hw_h + (size_t)rhi * D + col) = __floats2half2_rn(v2, v3);
        }
    }
#pragma unroll
    for (int mt = 0; mt < 2; mt++)
#pragma unroll
        for (int hf = 0; hf < 2; hf++) {
            float s = sp[mt][hf], d = dp[mt][hf];
            s += __shfl_xor_sync(0xffffffffu, s, 1);
            s += __shfl_xor_sync(0xffffffffu, s, 2);
            d += __shfl_xor_sync(0xffffffffu, d, 1);
            d += __shfl_xor_sync(0xffffffffu, d, 2);
            if (qk == 0) {
                int r = m0 + warpM * 32 + mt * 16 + groupr + hf * 8;
                if (r < NN) {
                    atomicAdd(&srcp[r], s);
                    atomicAdd(&dstp[r], d);
                }
            }
        }
}

// ---------------------------------------------------------------------------
// Attention + aggregation + ELU. One warp per node; fp16 gather + fp16 out.
// ---------------------------------------------------------------------------
__global__ void agg_kernel(const void* __restrict__ neighbors, int layer) {
    int w    = (blockIdx.x * blockDim.x + threadIdx.x) >> 5;
    int lane = threadIdx.x & 31;
    if (w >= NN) return;
    const float* srcp = g_src + layer * NN;
    const float* dstp = g_dst + layer * NN;

    int   nbr = 0;
    float e   = -1e30f;
    if (lane < KNB) {
        nbr = load_idx(neighbors, (long long)w * KNB + lane);
        e   = srcp[w] + dstp[nbr];
        e   = e > 0.f ? e : NEG_SLOPE * e;
    }
    float m = e;
#pragma unroll
    for (int o = 8; o > 0; o >>= 1) m = fmaxf(m, __shfl_xor_sync(0xffffffffu, m, o));
    float ex = (lane < KNB) ? __expf(e - m) : 0.f;
    float s = ex;
#pragma unroll
    for (int o = 8; o > 0; o >>= 1) s += __shfl_xor_sync(0xffffffffu, s, o);
    float alpha = ex / s;

    float acc[8] = {0.f, 0.f, 0.f, 0.f, 0.f, 0.f, 0.f, 0.f};
#pragma unroll
    for (int k = 0; k < KNB; k++) {
        float al  = __shfl_sync(0xffffffffu, alpha, k);
        int   idx = __shfl_sync(0xffffffffu, nbr, k);
        uint4 v = *((const uint4*)(g_hw_h + (size_t)idx * D) + lane);
        const __half2* hp = (const __half2*)&v;
        float2 f0 = __half22float2(hp[0]);
        float2 f1 = __half22float2(hp[1]);
        float2 f2 = __half22float2(hp[2]);
        float2 f3 = __half22float2(hp[3]);
        acc[0] += al * f0.x; acc[1] += al * f0.y;
        acc[2] += al * f1.x; acc[3] += al * f1.y;
        acc[4] += al * f2.x; acc[5] += al * f2.y;
        acc[6] += al * f3.x; acc[7] += al * f3.y;
    }
#pragma unroll
    for (int j = 0; j < 8; j++)
        acc[j] = acc[j] > 0.f ? acc[j] : __expf(acc[j]) - 1.f;

    uint4 ov;
    __half2* op = (__half2*)&ov;
    op[0] = __floats2half2_rn(acc[0], acc[1]);
    op[1] = __floats2half2_rn(acc[2], acc[3]);
    op[2] = __floats2half2_rn(acc[4], acc[5]);
    op[3] = __floats2half2_rn(acc[6], acc[7]);
    *((uint4*)(g_h16 + (size_t)w * D) + lane) = ov;
}

// ---------------------------------------------------------------------------
// Classification head.
// ---------------------------------------------------------------------------
__global__ void cls_kernel(const void* __restrict__ node,
                           const float* __restrict__ cls_W,
                           const float* __restrict__ cls_b,
                           float* __restrict__ out) {
    int b    = (blockIdx.x * blockDim.x + threadIdx.x) >> 5;
    int lane = threadIdx.x & 31;
    if (b >= NB) return;
    int n = load_idx(node, b);
    uint4 v = *((const uint4*)(g_h16 + (size_t)n * D) + lane);
    const __half2* hp = (const __half2*)&v;
    float2 f0 = __half22float2(hp[0]);
    float2 f1 = __half22float2(hp[1]);
    float2 f2 = __half22float2(hp[2]);
    float2 f3 = __half22float2(hp[3]);
    for (int c = 0; c < NC; c++) {
        const float4* wr = (const float4*)(cls_W + (size_t)c * D);
        float4 w0 = wr[lane * 2], w1 = wr[lane * 2 + 1];
        float p = f0.x * w0.x + f0.y * w0.y + f1.x * w0.z + f1.y * w0.w
                + f2.x * w1.x + f2.y * w1.y + f3.x * w1.z + f3.y * w1.w;
        p = warp_red_sum(p);
        if (lane == 0) out[(size_t)b * NC + c] = p + cls_b[c];
    }
}

// ---------------------------------------------------------------------------
extern "C" void kernel_launch(void* const* d_in, const int* in_sizes, int n_in,
                              void* d_out, int out_size) {
    const void*  node      = d_in[0];
    const float* node_feat = (const float*)d_in[1];
    const void*  neighbors = d_in[2];
    const float* Ws        = (const float*)d_in[3];
    const float* a_src     = (const float*)d_in[4];
    const float* a_dst     = (const float*)d_in[5];
    const float* cls_W     = (const float*)d_in[6];
    const float* cls_b     = (const float*)d_in[7];
    float* out = (float*)d_out;

    const int warp_blocks = (NN * 32 + 255) / 256;  // 6250

    int n_words = in_sizes[2] < 2048 ? in_sizes[2] : 2048;
    init_kernel<<<(2 * NN + 255) / 256, 256>>>(Ws, (const int*)neighbors, n_words);

    dim3 ggrid(D / GBN, (NN + GBM - 1) / GBM);      // (2, 391)
    tc_gemm_kernel<0><<<ggrid, 256>>>(node_feat, a_src, a_dst);
    agg_kernel<<<warp_blocks, 256>>>(neighbors, 0);
    tc_gemm_kernel<1><<<ggrid, 256>>>(node_feat, a_src + D, a_dst + D);
    agg_kernel<<<warp_blocks, 256>>>(neighbors, 1);
    cls_kernel<<<(NB * 32 + 255) / 256, 256>>>(node, cls_W, cls_b, out);
}